// round 1
// baseline (speedup 1.0000x reference)
#include <cuda_runtime.h>
#include <math.h>

#define NPART 4096
#define NC 16

// physics constants
__device__ __forceinline__ float d_alpha() { return 2.8f; }
#define R_ON2  (1.7f * 1.7f)       /* 2.89  */
#define R_C2   (4.0f)              /* 2.0^2 */
// 1 / (r_c^2 - r_o^2)^3
#define CUT_INV_DENOM (1.0f / ((R_C2 - R_ON2) * (R_C2 - R_ON2) * (R_C2 - R_ON2)))

// scratch (no allocations allowed)
__device__ float g_w[NPART * NC];     // w_i[d] = 0.5 * sum_c ct[c]*(E[c,d]+E[d,c])
__device__ float g_mask[NPART];       // column mask: sum(ct_j) > 0
__device__ float g_part[16 * 16];     // per-block partial sums

// ---------------------------------------------------------------------------
// Kernel 1: per-particle contraction w_i = ct_i^T E_sym_i, plus column mask
// ---------------------------------------------------------------------------
__global__ void prep_kernel(const float* __restrict__ ct,
                            const float* __restrict__ E) {
    int t = blockIdx.x * blockDim.x + threadIdx.x;
    if (t >= NPART * NC) return;
    int i = t >> 4;
    int d = t & 15;
    const float* cti = ct + i * NC;
    const float* Ei  = E  + i * NC * NC;
    float w = 0.0f;
#pragma unroll
    for (int c = 0; c < NC; c++) {
        w += cti[c] * (Ei[c * NC + d] + Ei[d * NC + c]);
    }
    g_w[t] = 0.5f * w;
    if (d == 0) {
        float s = 0.0f;
#pragma unroll
        for (int c = 0; c < NC; c++) s += cti[c];
        g_mask[i] = (s > 0.0f) ? 1.0f : 0.0f;
    }
}

// ---------------------------------------------------------------------------
// Kernel 2: O(N^2) distance screen with rare heavy path inside the cutoff
// grid = (16, 16), block = 256. blockIdx.x tiles i, blockIdx.y tiles j.
// ---------------------------------------------------------------------------
__global__ __launch_bounds__(256)
void pair_kernel(const float* __restrict__ pos,
                 const float* __restrict__ rad,
                 const float* __restrict__ ct) {
    __shared__ float4 spj[256];    // j-tile: x,y,z,radius
    __shared__ float  smask[256];  // j-tile: column mask

    const int tid   = threadIdx.x;
    const int i     = blockIdx.x * 256 + tid;
    const int jbase = blockIdx.y * 256;

    {
        int j = jbase + tid;
        spj[tid]   = make_float4(pos[3 * j], pos[3 * j + 1], pos[3 * j + 2], rad[j]);
        smask[tid] = g_mask[j];
    }
    __syncthreads();

    const float px = pos[3 * i];
    const float py = pos[3 * i + 1];
    const float pz = pos[3 * i + 2];
    const float ri = rad[i];
    const float* __restrict__ cti = ct  + i * NC;
    const float* __restrict__ wi  = g_w + i * NC;

    float acc = 0.0f;

#pragma unroll 4
    for (int jj = 0; jj < 256; jj++) {
        float4 pj = spj[jj];
        float dx = px - pj.x;
        float dy = py - pj.y;
        float dz = pz - pj.z;
        float r2 = dx * dx + dy * dy + dz * dz;
        int jg = jbase + jj;
        if (r2 < R_C2 && jg != i) {
            // --- heavy path: rare (~0.05% of pairs) ---
            float dr = sqrtf(r2);
            float cut;
            if (r2 < R_ON2) {
                cut = 1.0f;
            } else {
                float t = R_C2 - r2;
                cut = t * t * (R_C2 + 2.0f * r2 - 3.0f * R_ON2) * CUT_INV_DENOM;
            }
            float sigma = ri + pj.w;
            const float* __restrict__ ctj = ct  + jg * NC;
            const float* __restrict__ wj  = g_w + jg * NC;
            float dot = 0.0f;
#pragma unroll
            for (int c = 0; c < NC; c++) {
                dot += wi[c] * ctj[c] + wj[c] * cti[c];
            }
            float er  = 0.5f * dot;
            float eps = (5.0f / (1.0f + expf(-er)) + 0.3f) * smask[jj];
            float u   = 1.0f - expf(-d_alpha() * (dr - sigma));
            acc += eps * (u * u - 1.0f) * cut;
        }
    }

    // deterministic block tree-reduce
    __shared__ float red[256];
    red[tid] = acc;
    __syncthreads();
#pragma unroll
    for (int s = 128; s > 0; s >>= 1) {
        if (tid < s) red[tid] += red[tid + s];
        __syncthreads();
    }
    if (tid == 0) g_part[blockIdx.y * 16 + blockIdx.x] = red[0];
}

// ---------------------------------------------------------------------------
// Kernel 3: deterministic final reduction of 256 partials
// ---------------------------------------------------------------------------
__global__ void final_kernel(float* __restrict__ out) {
    __shared__ float red[256];
    int tid = threadIdx.x;
    red[tid] = g_part[tid];
    __syncthreads();
#pragma unroll
    for (int s = 128; s > 0; s >>= 1) {
        if (tid < s) red[tid] += red[tid + s];
        __syncthreads();
    }
    if (tid == 0) out[0] = 0.5f * red[0];
}

// ---------------------------------------------------------------------------
// Launch. Inputs (metadata order): position (N*3), celltype (N*16),
// epsilon (N*256), radius (N). Output: scalar float.
// ---------------------------------------------------------------------------
extern "C" void kernel_launch(void* const* d_in, const int* in_sizes, int n_in,
                              void* d_out, int out_size) {
    const float* pos = (const float*)d_in[0];
    const float* ct  = (const float*)d_in[1];
    const float* E   = (const float*)d_in[2];
    const float* rad = (const float*)d_in[3];
    float* out = (float*)d_out;

    prep_kernel<<<(NPART * NC + 255) / 256, 256>>>(ct, E);

    dim3 grid(16, 16);
    pair_kernel<<<grid, 256>>>(pos, rad, ct);

    final_kernel<<<1, 256>>>(out);
}

// round 2
// speedup vs baseline: 1.3574x; 1.3574x over previous
#include <cuda_runtime.h>
#include <math.h>

#define NPART 4096
#define NC 16

#define R_ON2  (1.7f * 1.7f)       /* 2.89  */
#define R_C2   (4.0f)              /* 2.0^2 */
#define CUT_INV_DENOM (1.0f / ((R_C2 - R_ON2) * (R_C2 - R_ON2) * (R_C2 - R_ON2)))
#define ALPHA_F 2.8f

// scratch (no allocations allowed)
__device__ float  g_w[NPART * NC];   // w_i[d] = 0.5 * sum_c ct[c]*(E[c,d]+E[d,c])
__device__ float  g_mask[NPART];     // column mask: sum(ct_j) > 0
__device__ float4 g_pos4[NPART];     // x,y,z,radius
__device__ float  g_part[512];       // per-block partial sums (grid 8x64)

// XOR-16 swizzle within a 256-float particle block: permutes within 16-float
// groups so both E[c*16+d] (d across threads) and E[d*16+c] (stride-16 across
// threads) hit distinct banks.
__device__ __forceinline__ int swz(int idx) { return idx ^ ((idx >> 4) & 15); }

// ---------------------------------------------------------------------------
// Kernel 1: per-particle contraction w_i = ct_i^T E_sym_i, mask, pos4 pack.
// block = 256 threads <-> 16 particles x 16 output dims. E staged in smem.
// ---------------------------------------------------------------------------
__global__ __launch_bounds__(256)
void prep_kernel(const float* __restrict__ pos,
                 const float* __restrict__ ct,
                 const float* __restrict__ E,
                 const float* __restrict__ rad) {
    __shared__ float sE[16 * 256];   // 16 KB, swizzled per particle
    __shared__ float sct[16 * NC];   // 1 KB

    const int tid  = threadIdx.x;
    const int base = blockIdx.x * 16;          // first particle of this block

    // coalesced stage of 16 particles' epsilon blocks (4096 floats)
    const float* __restrict__ Eb = E + base * 256;
#pragma unroll
    for (int k = 0; k < 16; k++) {
        int j = tid + k * 256;
        sE[swz(j)] = Eb[j];
    }
    sct[tid & 255 & (16 * NC - 1)] = 0.0f;     // placate compiler; overwritten below
    if (tid < 16 * NC) sct[tid] = ct[base * NC + tid];
    __syncthreads();

    const int p = tid >> 4;    // local particle 0..15
    const int d = tid & 15;    // output dim
    const int i = base + p;    // global particle

    float w = 0.0f;
#pragma unroll
    for (int c = 0; c < NC; c++) {
        float ctc = sct[p * NC + c];
        float e1  = sE[p * 256 + swz(c * 16 + d)];
        float e2  = sE[p * 256 + swz(d * 16 + c)];
        w += ctc * (e1 + e2);
    }
    g_w[i * NC + d] = 0.5f * w;

    if (d == 0) {
        float s = 0.0f;
#pragma unroll
        for (int c = 0; c < NC; c++) s += sct[p * NC + c];
        g_mask[i] = (s > 0.0f) ? 1.0f : 0.0f;
        g_pos4[i] = make_float4(pos[3 * i], pos[3 * i + 1], pos[3 * i + 2], rad[i]);
    }
}

// ---------------------------------------------------------------------------
// Heavy path: evaluated only for pairs inside the cutoff (~0.05%).
// ---------------------------------------------------------------------------
__device__ __noinline__ float pair_energy(float r2, float ri, float rj, float mj,
                                          const float* __restrict__ wi,
                                          const float* __restrict__ cti,
                                          int jg,
                                          const float* __restrict__ ct) {
    float dr = sqrtf(r2);
    float cut;
    if (r2 < R_ON2) {
        cut = 1.0f;
    } else {
        float t = R_C2 - r2;
        cut = t * t * (R_C2 + 2.0f * r2 - 3.0f * R_ON2) * CUT_INV_DENOM;
    }
    const float* __restrict__ ctj = ct  + jg * NC;
    const float* __restrict__ wj  = g_w + jg * NC;
    float dot = 0.0f;
#pragma unroll
    for (int c = 0; c < NC; c++) {
        dot += wi[c] * ctj[c] + wj[c] * cti[c];
    }
    float er  = 0.5f * dot;
    float eps = (5.0f / (1.0f + expf(-er)) + 0.3f) * mj;
    float u   = 1.0f - expf(-ALPHA_F * (dr - (ri + rj)));
    return eps * (u * u - 1.0f) * cut;
}

// ---------------------------------------------------------------------------
// Kernel 2: O(N^2) screen. grid (8, 64), block 256. Each thread handles
// 2 i-particles (i, i+256) against a 64-wide shared j-tile. All 512 blocks
// resident in one wave.
// ---------------------------------------------------------------------------
__global__ __launch_bounds__(256)
void pair_kernel(const float* __restrict__ ct) {
    __shared__ float4 spj[64];
    __shared__ float  smask[64];

    const int tid   = threadIdx.x;
    const int jbase = blockIdx.y * 64;

    if (tid < 64) {
        int j = jbase + tid;
        spj[tid]   = g_pos4[j];
        smask[tid] = g_mask[j];
    }
    __syncthreads();

    const int i0 = blockIdx.x * 512 + tid;
    const int i1 = i0 + 256;

    const float4 p0 = g_pos4[i0];
    const float4 p1 = g_pos4[i1];
    const float* __restrict__ w0  = g_w + i0 * NC;
    const float* __restrict__ w1  = g_w + i1 * NC;
    const float* __restrict__ ct0 = ct  + i0 * NC;
    const float* __restrict__ ct1 = ct  + i1 * NC;

    float acc0 = 0.0f, acc1 = 0.0f;

#pragma unroll 8
    for (int jj = 0; jj < 64; jj++) {
        float4 pj = spj[jj];
        float dx0 = p0.x - pj.x, dy0 = p0.y - pj.y, dz0 = p0.z - pj.z;
        float dx1 = p1.x - pj.x, dy1 = p1.y - pj.y, dz1 = p1.z - pj.z;
        float r20 = fmaf(dx0, dx0, fmaf(dy0, dy0, dz0 * dz0));
        float r21 = fmaf(dx1, dx1, fmaf(dy1, dy1, dz1 * dz1));
        if (r20 < R_C2 && r20 > 0.0f) {
            acc0 += pair_energy(r20, p0.w, pj.w, smask[jj], w0, ct0, jbase + jj, ct);
        }
        if (r21 < R_C2 && r21 > 0.0f) {
            acc1 += pair_energy(r21, p1.w, pj.w, smask[jj], w1, ct1, jbase + jj, ct);
        }
    }

    // deterministic block tree-reduce
    __shared__ float red[256];
    red[tid] = acc0 + acc1;
    __syncthreads();
#pragma unroll
    for (int s = 128; s > 0; s >>= 1) {
        if (tid < s) red[tid] += red[tid + s];
        __syncthreads();
    }
    if (tid == 0) g_part[blockIdx.y * 8 + blockIdx.x] = red[0];
}

// ---------------------------------------------------------------------------
// Kernel 3: deterministic final reduction of 512 partials
// ---------------------------------------------------------------------------
__global__ void final_kernel(float* __restrict__ out) {
    __shared__ float red[256];
    int tid = threadIdx.x;
    red[tid] = g_part[tid] + g_part[tid + 256];
    __syncthreads();
#pragma unroll
    for (int s = 128; s > 0; s >>= 1) {
        if (tid < s) red[tid] += red[tid + s];
        __syncthreads();
    }
    if (tid == 0) out[0] = 0.5f * red[0];
}

// ---------------------------------------------------------------------------
// Launch. Inputs (metadata order): position (N*3), celltype (N*16),
// epsilon (N*256), radius (N). Output: scalar float.
// ---------------------------------------------------------------------------
extern "C" void kernel_launch(void* const* d_in, const int* in_sizes, int n_in,
                              void* d_out, int out_size) {
    const float* pos = (const float*)d_in[0];
    const float* ct  = (const float*)d_in[1];
    const float* E   = (const float*)d_in[2];
    const float* rad = (const float*)d_in[3];
    float* out = (float*)d_out;

    prep_kernel<<<NPART / 16, 256>>>(pos, ct, E, rad);

    dim3 grid(8, 64);
    pair_kernel<<<grid, 256>>>(ct);

    final_kernel<<<1, 256>>>(out);
}